// round 1
// baseline (speedup 1.0000x reference)
#include <cuda_runtime.h>
#include <cstddef>

#define D 128
#define NODES_CAP 100000

// Scratch (allocation-free: __device__ globals)
__device__ float g_neigh[(size_t)NODES_CAP * D];   // segsum(nfeat[src]*w) by dst
__device__ float g_eagg [(size_t)NODES_CAP * D];   // segsum(efeat) by dst
__device__ float g_indeg[NODES_CAP];               // in-degree (float)

// ---------------------------------------------------------------------------
// Kernel 1: zero scratch
// ---------------------------------------------------------------------------
__global__ __launch_bounds__(256) void zero_kernel(int n_nodes)
{
    size_t total4 = (size_t)n_nodes * (D / 4);
    size_t i = (size_t)blockIdx.x * blockDim.x + threadIdx.x;
    float4 z = make_float4(0.f, 0.f, 0.f, 0.f);
    if (i < total4) {
        reinterpret_cast<float4*>(g_neigh)[i] = z;
        reinterpret_cast<float4*>(g_eagg)[i]  = z;
    }
    if (i < (size_t)n_nodes) g_indeg[i] = 0.f;
}

// ---------------------------------------------------------------------------
// Kernel 2: edge scatter. One warp per edge; lane l handles floats [4l, 4l+4).
// Vectorized no-return reductions (red.global.add.v4.f32).
// ---------------------------------------------------------------------------
__global__ __launch_bounds__(256) void scatter_kernel(
    const float* __restrict__ nfeat, const float* __restrict__ efeat,
    const float* __restrict__ ew, const int* __restrict__ src,
    const int* __restrict__ dst, int E)
{
    int e = blockIdx.x * 8 + (threadIdx.x >> 5);
    if (e >= E) return;
    int lane = threadIdx.x & 31;

    int   s = __ldg(src + e);
    int   d = __ldg(dst + e);
    float w = __ldg(ew + e);

    float4 a  = __ldg(reinterpret_cast<const float4*>(nfeat + (size_t)s * D) + lane);
    float4 ev = __ldg(reinterpret_cast<const float4*>(efeat + (size_t)e * D) + lane);

    float* np = g_neigh + (size_t)d * D + lane * 4;
    float* ep = g_eagg  + (size_t)d * D + lane * 4;

    asm volatile("red.global.add.v4.f32 [%0], {%1,%2,%3,%4};"
                 :: "l"(np), "f"(a.x * w), "f"(a.y * w), "f"(a.z * w), "f"(a.w * w)
                 : "memory");
    asm volatile("red.global.add.v4.f32 [%0], {%1,%2,%3,%4};"
                 :: "l"(ep), "f"(ev.x), "f"(ev.y), "f"(ev.z), "f"(ev.w)
                 : "memory");
    if (lane == 0) {
        asm volatile("red.global.add.f32 [%0], %1;"
                     :: "l"(g_indeg + d), "f"(1.0f) : "memory");
    }
}

// ---------------------------------------------------------------------------
// Kernel 3: fused node GEMM.
//   X[m, k]      = (neigh[m,k] + 2*nfeat[m,k]) / (indeg[m]+1)      (k in [0,128))
//   X[m, 128+k]  = eagg[m,k] / max(indeg[m],1)                     (k in [0,128))
//   out[m, o]    = sum_k X[m,k] * Wcat[o,k] + bn[o] + [indeg>0]*be[o]
// Block tile: 128 nodes x 128 outputs, 256 threads, 8x8 register tile, K=256.
// ---------------------------------------------------------------------------
__global__ __launch_bounds__(256) void node_gemm(
    const float* __restrict__ nfeat,
    const float* __restrict__ Wn, const float* __restrict__ bn,
    const float* __restrict__ We, const float* __restrict__ be,
    float* __restrict__ out, int Nn)
{
    __shared__ float sX[8][128];
    __shared__ float sW[8][128];
    __shared__ float sInvD[128];
    __shared__ float sInvE[128];
    __shared__ float sHasE[128];

    const int tid   = threadIdx.x;
    const int mBase = blockIdx.x * 128;

    if (tid < 128) {
        int m  = mBase + tid;
        int mc = (m < Nn) ? m : (Nn - 1);
        float id = g_indeg[mc];
        sInvD[tid] = 1.f / (id + 1.f);
        sInvE[tid] = 1.f / fmaxf(id, 1.f);
        sHasE[tid] = (id > 0.5f) ? 1.f : 0.f;
    }
    __syncthreads();

    const int tx = tid & 15;    // output group: o = tx*8 + j
    const int ty = tid >> 4;    // node group:   m = mBase + ty*8 + i

    float acc[8][8];
    #pragma unroll
    for (int i = 0; i < 8; i++)
        #pragma unroll
        for (int j = 0; j < 8; j++) acc[i][j] = 0.f;

    const int lm = tid & 127;        // loader row (node or output index)
    const int lk = (tid >> 7) * 4;   // loader k sub-offset: 0 or 4

    for (int kt = 0; kt < 256; kt += 8) {
        // --- stage W tile: sW[kk][o] ---
        {
            const float* Wsrc = (kt < 128) ? Wn : We;
            int kg = (kt < 128) ? kt : (kt - 128);
            float4 wv = *reinterpret_cast<const float4*>(Wsrc + (size_t)lm * D + kg + lk);
            sW[lk + 0][lm] = wv.x; sW[lk + 1][lm] = wv.y;
            sW[lk + 2][lm] = wv.z; sW[lk + 3][lm] = wv.w;
        }
        // --- stage X tile: sX[kk][m] (computed on the fly) ---
        {
            int m  = mBase + lm;
            int mc = (m < Nn) ? m : (Nn - 1);
            if (kt < 128) {
                float4 nv = *reinterpret_cast<const float4*>(g_neigh + (size_t)mc * D + kt + lk);
                float4 fv = *reinterpret_cast<const float4*>(nfeat   + (size_t)mc * D + kt + lk);
                float sc = sInvD[lm];
                sX[lk + 0][lm] = (nv.x + 2.f * fv.x) * sc;
                sX[lk + 1][lm] = (nv.y + 2.f * fv.y) * sc;
                sX[lk + 2][lm] = (nv.z + 2.f * fv.z) * sc;
                sX[lk + 3][lm] = (nv.w + 2.f * fv.w) * sc;
            } else {
                float4 gv = *reinterpret_cast<const float4*>(g_eagg + (size_t)mc * D + (kt - 128) + lk);
                float sc = sInvE[lm];
                sX[lk + 0][lm] = gv.x * sc;
                sX[lk + 1][lm] = gv.y * sc;
                sX[lk + 2][lm] = gv.z * sc;
                sX[lk + 3][lm] = gv.w * sc;
            }
        }
        __syncthreads();

        #pragma unroll
        for (int kk = 0; kk < 8; kk++) {
            float a[8], b[8];
            *reinterpret_cast<float4*>(a)     = *reinterpret_cast<float4*>(&sX[kk][ty * 8]);
            *reinterpret_cast<float4*>(a + 4) = *reinterpret_cast<float4*>(&sX[kk][ty * 8 + 4]);
            *reinterpret_cast<float4*>(b)     = *reinterpret_cast<float4*>(&sW[kk][tx * 8]);
            *reinterpret_cast<float4*>(b + 4) = *reinterpret_cast<float4*>(&sW[kk][tx * 8 + 4]);
            #pragma unroll
            for (int i = 0; i < 8; i++)
                #pragma unroll
                for (int j = 0; j < 8; j++)
                    acc[i][j] += a[i] * b[j];
        }
        __syncthreads();
    }

    // --- epilogue: bias + store ---
    const int oBase = tx * 8;
    float bnv[8], bev[8];
    #pragma unroll
    for (int j = 0; j < 8; j++) {
        bnv[j] = __ldg(bn + oBase + j);
        bev[j] = __ldg(be + oBase + j);
    }
    #pragma unroll
    for (int i = 0; i < 8; i++) {
        int m = mBase + ty * 8 + i;
        if (m < Nn) {
            float he = sHasE[ty * 8 + i];
            float v[8];
            #pragma unroll
            for (int j = 0; j < 8; j++)
                v[j] = acc[i][j] + bnv[j] + he * bev[j];
            *reinterpret_cast<float4*>(out + (size_t)m * D + oBase)     =
                make_float4(v[0], v[1], v[2], v[3]);
            *reinterpret_cast<float4*>(out + (size_t)m * D + oBase + 4) =
                make_float4(v[4], v[5], v[6], v[7]);
        }
    }
}

// ---------------------------------------------------------------------------
extern "C" void kernel_launch(void* const* d_in, const int* in_sizes, int n_in,
                              void* d_out, int out_size)
{
    const float* nfeat = (const float*)d_in[0];
    const float* efeat = (const float*)d_in[1];
    const float* ew    = (const float*)d_in[2];
    const float* Wn    = (const float*)d_in[3];
    const float* bn    = (const float*)d_in[4];
    const float* We    = (const float*)d_in[5];
    const float* be    = (const float*)d_in[6];
    const int*   src   = (const int*)d_in[7];
    const int*   dst   = (const int*)d_in[8];
    float* out = (float*)d_out;

    int Nn = in_sizes[0] / D;     // 100000
    int E  = in_sizes[2];         // 1600000

    int zthreads = Nn * (D / 4);
    zero_kernel<<<(zthreads + 255) / 256, 256>>>(Nn);
    scatter_kernel<<<(E + 7) / 8, 256>>>(nfeat, efeat, ew, src, dst, E);
    node_gemm<<<(Nn + 127) / 128, 256>>>(nfeat, Wn, bn, We, be, out, Nn);
}

// round 2
// speedup vs baseline: 1.3838x; 1.3838x over previous
#include <cuda_runtime.h>
#include <cstddef>

#define D 128
#define NODES_CAP 100000
#define EDGES_CAP 1600000
#define SCAN_B 1024

// ---------------- scratch (__device__ globals; no allocation) ---------------
__device__ int   g_counts[NODES_CAP];              // in-degree
__device__ int   g_offs  [NODES_CAP];              // exclusive start; becomes end after scatter_ids
__device__ int   g_bsum  [128];                    // block partial sums for scan
__device__ int   g_perm  [EDGES_CAP];              // edge ids sorted by dst
__device__ float g_x     [(size_t)NODES_CAP * 256];// normalized GEMM input [n][256]

// ---------------------------------------------------------------------------
__global__ __launch_bounds__(256) void zero_counts(int n)
{
    int i = blockIdx.x * 256 + threadIdx.x;
    if (i < n) g_counts[i] = 0;
}

__global__ __launch_bounds__(256) void hist_kernel(const int* __restrict__ dst, int E)
{
    int e = blockIdx.x * 256 + threadIdx.x;
    if (e < E) atomicAdd(&g_counts[dst[e]], 1);
}

// exclusive scan within 1024-block; write block total
__global__ __launch_bounds__(SCAN_B) void scan1(int n)
{
    __shared__ int wsum[32];
    int i = blockIdx.x * SCAN_B + threadIdx.x;
    int v = (i < n) ? g_counts[i] : 0;
    int x = v;
    #pragma unroll
    for (int d = 1; d < 32; d <<= 1) {
        int y = __shfl_up_sync(0xffffffffu, x, d);
        if ((threadIdx.x & 31) >= d) x += y;
    }
    if ((threadIdx.x & 31) == 31) wsum[threadIdx.x >> 5] = x;
    __syncthreads();
    if (threadIdx.x < 32) {
        int y = wsum[threadIdx.x];
        #pragma unroll
        for (int d = 1; d < 32; d <<= 1) {
            int z = __shfl_up_sync(0xffffffffu, y, d);
            if (threadIdx.x >= d) y += z;
        }
        wsum[threadIdx.x] = y;
    }
    __syncthreads();
    int base = (threadIdx.x >= 32) ? wsum[(threadIdx.x >> 5) - 1] : 0;
    int incl = base + x;
    if (i < n) g_offs[i] = incl - v;
    if (threadIdx.x == SCAN_B - 1) g_bsum[blockIdx.x] = incl;
}

__global__ void scan2(int nb)
{
    if (threadIdx.x == 0) {
        int run = 0;
        for (int b = 0; b < nb; b++) { int t = g_bsum[b]; g_bsum[b] = run; run += t; }
    }
}

__global__ __launch_bounds__(SCAN_B) void scan3(int n)
{
    int i = blockIdx.x * SCAN_B + threadIdx.x;
    if (i < n) g_offs[i] += g_bsum[blockIdx.x];
}

// post-increment on g_offs: afterwards g_offs[n] == segment END
__global__ __launch_bounds__(256) void scatter_ids(const int* __restrict__ dst, int E)
{
    int e = blockIdx.x * 256 + threadIdx.x;
    if (e < E) {
        int p = atomicAdd(&g_offs[dst[e]], 1);
        g_perm[p] = e;
    }
}

// ---------------------------------------------------------------------------
// Warp-per-node atomic-free aggregation. Writes normalized X row directly:
//   X[n][k]     = (sum_e w_e*nfeat[src_e][k] + 2*nfeat[n][k]) / (deg+1)
//   X[n][128+k] = (sum_e efeat[e][k]) / max(deg,1)
// ---------------------------------------------------------------------------
__global__ __launch_bounds__(256) void aggregate_kernel(
    const float* __restrict__ nfeat, const float* __restrict__ efeat,
    const float* __restrict__ ew, const int* __restrict__ src, int Nn)
{
    int n = blockIdx.x * 8 + (threadIdx.x >> 5);
    if (n >= Nn) return;
    int lane = threadIdx.x & 31;

    int end = g_offs[n];
    int cnt = g_counts[n];
    int beg = end - cnt;

    const float4* nf4 = reinterpret_cast<const float4*>(nfeat);
    const float4* ef4 = reinterpret_cast<const float4*>(efeat);

    float4 aN = make_float4(0.f, 0.f, 0.f, 0.f);
    float4 aE = make_float4(0.f, 0.f, 0.f, 0.f);

    int i = beg;
    for (; i + 2 <= end; i += 2) {
        int e0 = g_perm[i], e1 = g_perm[i + 1];
        int s0 = __ldg(src + e0), s1 = __ldg(src + e1);
        float w0 = __ldg(ew + e0), w1 = __ldg(ew + e1);
        float4 a0 = __ldg(nf4 + (size_t)s0 * 32 + lane);
        float4 a1 = __ldg(nf4 + (size_t)s1 * 32 + lane);
        float4 v0 = __ldg(ef4 + (size_t)e0 * 32 + lane);
        float4 v1 = __ldg(ef4 + (size_t)e1 * 32 + lane);
        aN.x += a0.x * w0 + a1.x * w1;  aN.y += a0.y * w0 + a1.y * w1;
        aN.z += a0.z * w0 + a1.z * w1;  aN.w += a0.w * w0 + a1.w * w1;
        aE.x += v0.x + v1.x;  aE.y += v0.y + v1.y;
        aE.z += v0.z + v1.z;  aE.w += v0.w + v1.w;
    }
    if (i < end) {
        int e0 = g_perm[i];
        int s0 = __ldg(src + e0);
        float w0 = __ldg(ew + e0);
        float4 a0 = __ldg(nf4 + (size_t)s0 * 32 + lane);
        float4 v0 = __ldg(ef4 + (size_t)e0 * 32 + lane);
        aN.x += a0.x * w0;  aN.y += a0.y * w0;  aN.z += a0.z * w0;  aN.w += a0.w * w0;
        aE.x += v0.x;  aE.y += v0.y;  aE.z += v0.z;  aE.w += v0.w;
    }

    float invD = 1.f / ((float)cnt + 1.f);
    float invE = 1.f / (float)max(cnt, 1);
    float4 f = __ldg(nf4 + (size_t)n * 32 + lane);

    float4 xn = make_float4((aN.x + 2.f * f.x) * invD, (aN.y + 2.f * f.y) * invD,
                            (aN.z + 2.f * f.z) * invD, (aN.w + 2.f * f.w) * invD);
    float4 xe = make_float4(aE.x * invE, aE.y * invE, aE.z * invE, aE.w * invE);

    float4* xr = reinterpret_cast<float4*>(g_x + (size_t)n * 256);
    xr[lane]      = xn;
    xr[32 + lane] = xe;
}

// ---------------------------------------------------------------------------
// GEMM: out[m][o] = sum_{k<256} X[m][k] * Wcat[o][k] + bn[o] + hasE[m]*be[o]
// 128x128 block tile, 256 threads, 8x8 reg tile, packed fma.rn.f32x2.
// ---------------------------------------------------------------------------
#define PACK2(r, x, y)  asm("mov.b64 %0, {%1,%2};" : "=l"(r) : "f"(x), "f"(y))
#define UNPACK2(x, y, r) asm("mov.b64 {%0,%1}, %2;" : "=f"(x), "=f"(y) : "l"(r))
#define FMA2(acc, a, b) asm("fma.rn.f32x2 %0, %1, %2, %0;" : "+l"(acc) : "l"(a), "l"(b))

__global__ __launch_bounds__(256) void node_gemm(
    const float* __restrict__ Wn, const float* __restrict__ bn,
    const float* __restrict__ We, const float* __restrict__ be,
    float* __restrict__ out, int Nn)
{
    __shared__ float sX[16][128];
    __shared__ float sW[16][128];
    __shared__ float sHasE[128];

    const int tid   = threadIdx.x;
    const int mBase = blockIdx.x * 128;

    if (tid < 128) {
        int m  = mBase + tid;
        int mc = (m < Nn) ? m : (Nn - 1);
        sHasE[tid] = (g_counts[mc] > 0) ? 1.f : 0.f;
    }

    const int tx = tid & 15;    // output group: o = tx*8 + j
    const int ty = tid >> 4;    // node group:   m = mBase + ty*8 + i

    unsigned long long acc2[8][4];
    #pragma unroll
    for (int i = 0; i < 8; i++)
        #pragma unroll
        for (int j = 0; j < 4; j++) acc2[i][j] = 0ULL;

    const int lrow  = tid & 127;       // loader row
    const int lhalf = (tid >> 7) * 8;  // k sub-offset: 0 or 8
    __syncthreads();

    for (int kt = 0; kt < 256; kt += 16) {
        // stage W tile: sW[kk][o]
        {
            const float* Wsrc = (kt < 128) ? Wn : We;
            int kg = (kt & 127) + lhalf;
            float4 w0 = *reinterpret_cast<const float4*>(Wsrc + (size_t)lrow * D + kg);
            float4 w1 = *reinterpret_cast<const float4*>(Wsrc + (size_t)lrow * D + kg + 4);
            sW[lhalf + 0][lrow] = w0.x; sW[lhalf + 1][lrow] = w0.y;
            sW[lhalf + 2][lrow] = w0.z; sW[lhalf + 3][lrow] = w0.w;
            sW[lhalf + 4][lrow] = w1.x; sW[lhalf + 5][lrow] = w1.y;
            sW[lhalf + 6][lrow] = w1.z; sW[lhalf + 7][lrow] = w1.w;
        }
        // stage X tile: sX[kk][m]
        {
            int m  = mBase + lrow;
            int mc = (m < Nn) ? m : (Nn - 1);
            const float* xp = g_x + (size_t)mc * 256 + kt + lhalf;
            float4 x0 = *reinterpret_cast<const float4*>(xp);
            float4 x1 = *reinterpret_cast<const float4*>(xp + 4);
            sX[lhalf + 0][lrow] = x0.x; sX[lhalf + 1][lrow] = x0.y;
            sX[lhalf + 2][lrow] = x0.z; sX[lhalf + 3][lrow] = x0.w;
            sX[lhalf + 4][lrow] = x1.x; sX[lhalf + 5][lrow] = x1.y;
            sX[lhalf + 6][lrow] = x1.z; sX[lhalf + 7][lrow] = x1.w;
        }
        __syncthreads();

        #pragma unroll
        for (int kk = 0; kk < 16; kk++) {
            float4 xa = *reinterpret_cast<float4*>(&sX[kk][ty * 8]);
            float4 xb = *reinterpret_cast<float4*>(&sX[kk][ty * 8 + 4]);
            float4 wa = *reinterpret_cast<float4*>(&sW[kk][tx * 8]);
            float4 wb = *reinterpret_cast<float4*>(&sW[kk][tx * 8 + 4]);
            unsigned long long b2[4];
            PACK2(b2[0], wa.x, wa.y); PACK2(b2[1], wa.z, wa.w);
            PACK2(b2[2], wb.x, wb.y); PACK2(b2[3], wb.z, wb.w);
            float a[8] = {xa.x, xa.y, xa.z, xa.w, xb.x, xb.y, xb.z, xb.w};
            #pragma unroll
            for (int i = 0; i < 8; i++) {
                unsigned long long a2;
                PACK2(a2, a[i], a[i]);
                #pragma unroll
                for (int j = 0; j < 4; j++) FMA2(acc2[i][j], a2, b2[j]);
            }
        }
        __syncthreads();
    }

    // epilogue
    const int oBase = tx * 8;
    float bnv[8], bev[8];
    #pragma unroll
    for (int j = 0; j < 8; j++) {
        bnv[j] = __ldg(bn + oBase + j);
        bev[j] = __ldg(be + oBase + j);
    }
    #pragma unroll
    for (int i = 0; i < 8; i++) {
        int m = mBase + ty * 8 + i;
        if (m < Nn) {
            float he = sHasE[ty * 8 + i];
            float v[8];
            #pragma unroll
            for (int j = 0; j < 4; j++) {
                float lo, hi;
                UNPACK2(lo, hi, acc2[i][j]);
                v[2 * j]     = lo + bnv[2 * j]     + he * bev[2 * j];
                v[2 * j + 1] = hi + bnv[2 * j + 1] + he * bev[2 * j + 1];
            }
            *reinterpret_cast<float4*>(out + (size_t)m * D + oBase) =
                make_float4(v[0], v[1], v[2], v[3]);
            *reinterpret_cast<float4*>(out + (size_t)m * D + oBase + 4) =
                make_float4(v[4], v[5], v[6], v[7]);
        }
    }
}

// ---------------------------------------------------------------------------
extern "C" void kernel_launch(void* const* d_in, const int* in_sizes, int n_in,
                              void* d_out, int out_size)
{
    const float* nfeat = (const float*)d_in[0];
    const float* efeat = (const float*)d_in[1];
    const float* ew    = (const float*)d_in[2];
    const float* Wn    = (const float*)d_in[3];
    const float* bn    = (const float*)d_in[4];
    const float* We    = (const float*)d_in[5];
    const float* be    = (const float*)d_in[6];
    const int*   src   = (const int*)d_in[7];
    const int*   dst   = (const int*)d_in[8];
    float* out = (float*)d_out;

    int Nn = in_sizes[0] / D;     // 100000
    int E  = in_sizes[2];         // 1600000
    int nScanBlocks = (Nn + SCAN_B - 1) / SCAN_B;

    zero_counts<<<(Nn + 255) / 256, 256>>>(Nn);
    hist_kernel<<<(E + 255) / 256, 256>>>(dst, E);
    scan1<<<nScanBlocks, SCAN_B>>>(Nn);
    scan2<<<1, 32>>>(nScanBlocks);
    scan3<<<nScanBlocks, SCAN_B>>>(Nn);
    scatter_ids<<<(E + 255) / 256, 256>>>(dst, E);
    aggregate_kernel<<<(Nn + 7) / 8, 256>>>(nfeat, efeat, ew, src, Nn);
    node_gemm<<<(Nn + 127) / 128, 256>>>(Wn, bn, We, be, out, Nn);
}

// round 4
// speedup vs baseline: 1.7645x; 1.2751x over previous
#include <cuda_runtime.h>
#include <cuda_bf16.h>
#include <cstddef>
#include <cstdint>

#define D 128
#define NODES_CAP 100000
#define EDGES_CAP 1600000
#define SCAN_B 1024

// ---------------- scratch (__device__ globals; no allocation) ---------------
__device__ int   g_counts[NODES_CAP];
__device__ int   g_offs  [NODES_CAP];
__device__ int   g_bsum  [128];
__device__ int   g_perm  [EDGES_CAP];              // edge ids sorted by dst
__device__ int2  g_sw    [EDGES_CAP];              // (src, ew bits) sorted by dst
__device__ __nv_bfloat16 g_xh[(size_t)NODES_CAP * 256];  // X hi plane
__device__ __nv_bfloat16 g_xm[(size_t)NODES_CAP * 256];  // X mid plane
__device__ __nv_bfloat16 g_wh[128 * 256];                // Wcat hi   [o][k]
__device__ __nv_bfloat16 g_wm[128 * 256];                // Wcat mid  [o][k]

// ---------------------------------------------------------------------------
__global__ __launch_bounds__(256) void zero_counts(int n)
{
    int i = blockIdx.x * 256 + threadIdx.x;
    if (i < n) g_counts[i] = 0;
}

__global__ __launch_bounds__(256) void hist_kernel(const int* __restrict__ dst, int E)
{
    int e = blockIdx.x * 256 + threadIdx.x;
    if (e < E) atomicAdd(&g_counts[dst[e]], 1);
}

__global__ __launch_bounds__(SCAN_B) void scan1(int n)
{
    __shared__ int wsum[32];
    int i = blockIdx.x * SCAN_B + threadIdx.x;
    int v = (i < n) ? g_counts[i] : 0;
    int x = v;
    #pragma unroll
    for (int d = 1; d < 32; d <<= 1) {
        int y = __shfl_up_sync(0xffffffffu, x, d);
        if ((threadIdx.x & 31) >= d) x += y;
    }
    if ((threadIdx.x & 31) == 31) wsum[threadIdx.x >> 5] = x;
    __syncthreads();
    if (threadIdx.x < 32) {
        int y = wsum[threadIdx.x];
        #pragma unroll
        for (int d = 1; d < 32; d <<= 1) {
            int z = __shfl_up_sync(0xffffffffu, y, d);
            if (threadIdx.x >= d) y += z;
        }
        wsum[threadIdx.x] = y;
    }
    __syncthreads();
    int base = (threadIdx.x >= 32) ? wsum[(threadIdx.x >> 5) - 1] : 0;
    int incl = base + x;
    if (i < n) g_offs[i] = incl - v;
    if (threadIdx.x == SCAN_B - 1) g_bsum[blockIdx.x] = incl;
}

__global__ __launch_bounds__(128) void scan2(int nb)
{
    __shared__ int ws[4];
    int tid = threadIdx.x;
    int v = (tid < nb) ? g_bsum[tid] : 0;
    int x = v;
    #pragma unroll
    for (int d = 1; d < 32; d <<= 1) {
        int y = __shfl_up_sync(0xffffffffu, x, d);
        if ((tid & 31) >= d) x += y;
    }
    if ((tid & 31) == 31) ws[tid >> 5] = x;
    __syncthreads();
    if (tid == 0) { int r = 0; for (int i = 0; i < 4; i++) { int t = ws[i]; ws[i] = r; r += t; } }
    __syncthreads();
    int incl = x + ws[tid >> 5];
    if (tid < nb) g_bsum[tid] = incl - v;
}

__global__ __launch_bounds__(SCAN_B) void scan3(int n)
{
    int i = blockIdx.x * SCAN_B + threadIdx.x;
    if (i < n) g_offs[i] += g_bsum[blockIdx.x];
}

__global__ __launch_bounds__(256) void scatter_ids(
    const int* __restrict__ dst, const int* __restrict__ src,
    const float* __restrict__ ew, int E)
{
    int e = blockIdx.x * 256 + threadIdx.x;
    if (e < E) {
        int p = atomicAdd(&g_offs[dst[e]], 1);
        g_perm[p] = e;
        g_sw[p] = make_int2(src[e], __float_as_int(ew[e]));
    }
}

// weight split prep: Wcat[o][k] -> bf16 hi/mid planes, row-major [o][256]
__global__ __launch_bounds__(256) void wprep(const float* __restrict__ Wn,
                                             const float* __restrict__ We)
{
    int i = blockIdx.x * 256 + threadIdx.x;
    if (i >= 128 * 256) return;
    int o = i >> 8, k = i & 255;
    float w = (k < 128) ? Wn[o * 128 + k] : We[o * 128 + (k - 128)];
    __nv_bfloat16 h = __float2bfloat16(w);
    g_wh[i] = h;
    g_wm[i] = __float2bfloat16(w - __bfloat162float(h));
}

// ---------------------------------------------------------------------------
// Warp-per-node aggregation -> normalized X, written as bf16 hi/mid planes.
// ---------------------------------------------------------------------------
__device__ __forceinline__ uint2 pack4_hi(float4 v, float4* resid)
{
    __nv_bfloat162 p0 = __floats2bfloat162_rn(v.x, v.y);
    __nv_bfloat162 p1 = __floats2bfloat162_rn(v.z, v.w);
    resid->x = v.x - __bfloat162float(__low2bfloat16(p0));
    resid->y = v.y - __bfloat162float(__high2bfloat16(p0));
    resid->z = v.z - __bfloat162float(__low2bfloat16(p1));
    resid->w = v.w - __bfloat162float(__high2bfloat16(p1));
    uint2 r;
    r.x = *reinterpret_cast<unsigned*>(&p0);
    r.y = *reinterpret_cast<unsigned*>(&p1);
    return r;
}
__device__ __forceinline__ uint2 pack4(float4 v)
{
    __nv_bfloat162 p0 = __floats2bfloat162_rn(v.x, v.y);
    __nv_bfloat162 p1 = __floats2bfloat162_rn(v.z, v.w);
    uint2 r;
    r.x = *reinterpret_cast<unsigned*>(&p0);
    r.y = *reinterpret_cast<unsigned*>(&p1);
    return r;
}

__global__ __launch_bounds__(256) void aggregate_kernel(
    const float* __restrict__ nfeat, const float* __restrict__ efeat, int Nn)
{
    int n = blockIdx.x * 8 + (threadIdx.x >> 5);
    if (n >= Nn) return;
    int lane = threadIdx.x & 31;

    int end = g_offs[n];
    int cnt = g_counts[n];
    int beg = end - cnt;

    const float4* nf4 = reinterpret_cast<const float4*>(nfeat);
    const float4* ef4 = reinterpret_cast<const float4*>(efeat);

    float4 aN = make_float4(0.f, 0.f, 0.f, 0.f);
    float4 aE = make_float4(0.f, 0.f, 0.f, 0.f);

    int i = beg;
    for (; i + 2 <= end; i += 2) {
        int2 s0 = g_sw[i], s1 = g_sw[i + 1];
        int e0 = g_perm[i], e1 = g_perm[i + 1];
        float w0 = __int_as_float(s0.y), w1 = __int_as_float(s1.y);
        float4 a0 = __ldg(nf4 + (size_t)s0.x * 32 + lane);
        float4 a1 = __ldg(nf4 + (size_t)s1.x * 32 + lane);
        float4 v0 = __ldg(ef4 + (size_t)e0 * 32 + lane);
        float4 v1 = __ldg(ef4 + (size_t)e1 * 32 + lane);
        aN.x += a0.x * w0 + a1.x * w1;  aN.y += a0.y * w0 + a1.y * w1;
        aN.z += a0.z * w0 + a1.z * w1;  aN.w += a0.w * w0 + a1.w * w1;
        aE.x += v0.x + v1.x;  aE.y += v0.y + v1.y;
        aE.z += v0.z + v1.z;  aE.w += v0.w + v1.w;
    }
    if (i < end) {
        int2 s0 = g_sw[i];
        int e0 = g_perm[i];
        float w0 = __int_as_float(s0.y);
        float4 a0 = __ldg(nf4 + (size_t)s0.x * 32 + lane);
        float4 v0 = __ldg(ef4 + (size_t)e0 * 32 + lane);
        aN.x += a0.x * w0;  aN.y += a0.y * w0;  aN.z += a0.z * w0;  aN.w += a0.w * w0;
        aE.x += v0.x;  aE.y += v0.y;  aE.z += v0.z;  aE.w += v0.w;
    }

    float invD = 1.f / ((float)cnt + 1.f);
    float invE = 1.f / (float)max(cnt, 1);
    float4 f = __ldg(nf4 + (size_t)n * 32 + lane);

    float4 xn = make_float4((aN.x + 2.f * f.x) * invD, (aN.y + 2.f * f.y) * invD,
                            (aN.z + 2.f * f.z) * invD, (aN.w + 2.f * f.w) * invD);
    float4 xe = make_float4(aE.x * invE, aE.y * invE, aE.z * invE, aE.w * invE);

    uint2* xh = reinterpret_cast<uint2*>(g_xh + (size_t)n * 256);
    uint2* xm = reinterpret_cast<uint2*>(g_xm + (size_t)n * 256);
    float4 r;
    xh[lane] = pack4_hi(xn, &r);       xm[lane] = pack4(r);
    xh[32 + lane] = pack4_hi(xe, &r);  xm[32 + lane] = pack4(r);
}

// ---------------------------------------------------------------------------
// HMMA GEMM via mma.sync.m16n8k16.bf16 (baseline PTX; no 'a' features).
// out[m][o] = sum_k X[m][k]*W[o][k] + bn[o] + hasE[m]*be[o]
// 3-split: Xh*Wh + Xh*Wm + Xm*Wh.
// Block: 128(M) x 128(N), 256 threads = 8 warps (4 M x 2 N), warp tile 32x64.
// K staged in 8 chunks of 32. Smem pitch 40 bf16 -> conflict-free ldmatrix.
// ---------------------------------------------------------------------------
#define LDMX4(r0, r1, r2, r3, addr)                                                \
    asm volatile("ldmatrix.sync.aligned.m8n8.x4.shared.b16 {%0,%1,%2,%3}, [%4];"   \
                 : "=r"(r0), "=r"(r1), "=r"(r2), "=r"(r3) : "r"(addr))

#define MMA16816(d, a, b0, b1)                                                     \
    asm volatile("mma.sync.aligned.m16n8k16.row.col.f32.bf16.bf16.f32 "            \
                 "{%0,%1,%2,%3},{%4,%5,%6,%7},{%8,%9},{%0,%1,%2,%3};"              \
                 : "+f"((d)[0]), "+f"((d)[1]), "+f"((d)[2]), "+f"((d)[3])          \
                 : "r"((a)[0]), "r"((a)[1]), "r"((a)[2]), "r"((a)[3]),             \
                   "r"(b0), "r"(b1))

#define PITCH 40

__global__ __launch_bounds__(256) void gemm_mma(
    const float* __restrict__ bn, const float* __restrict__ be,
    float* __restrict__ out, int Nn)
{
    __shared__ __align__(16) __nv_bfloat16 sAh[128][PITCH];
    __shared__ __align__(16) __nv_bfloat16 sAm[128][PITCH];
    __shared__ __align__(16) __nv_bfloat16 sWh[128][PITCH];
    __shared__ __align__(16) __nv_bfloat16 sWm[128][PITCH];

    const int tid  = threadIdx.x;
    const int wid  = tid >> 5;
    const int lane = tid & 31;
    const int warpM = wid & 3;       // 4 slices of 32 rows
    const int warpN = wid >> 2;      // 2 slices of 64 cols
    const int mBase = blockIdx.x * 128;

    float d[2][8][4];
    #pragma unroll
    for (int mt = 0; mt < 2; mt++)
        #pragma unroll
        for (int nt = 0; nt < 8; nt++)
            #pragma unroll
            for (int c = 0; c < 4; c++) d[mt][nt][c] = 0.f;

    // loaders: 2 threads per row, each 2 x uint4 (32B) of the 64B k-chunk
    const int lrow = tid >> 1;
    const int lt   = (tid & 1) * 2;
    int arow = mBase + lrow; if (arow >= Nn) arow = Nn - 1;
    const uint4* gAh = reinterpret_cast<const uint4*>(g_xh + (size_t)arow * 256);
    const uint4* gAm = reinterpret_cast<const uint4*>(g_xm + (size_t)arow * 256);
    const uint4* gWh = reinterpret_cast<const uint4*>(g_wh + (size_t)lrow * 256);
    const uint4* gWm = reinterpret_cast<const uint4*>(g_wm + (size_t)lrow * 256);

    // ldmatrix lane geometry
    const int rA = (lane & 7) + ((lane >> 3) & 1) * 8;   // m row within 16
    const int cA = (lane >> 4) * 8;                      // k offset within 16
    const int rB = (lane & 7) + ((lane >> 4) & 1) * 8;   // n row within 16
    const int cB = ((lane >> 3) & 1) * 8;                // k offset within 16

    for (int kc = 0; kc < 8; kc++) {
        #pragma unroll
        for (int t = 0; t < 2; t++) {
            int gi = kc * 4 + lt + t;
            int so = (lt + t) * 8;
            *reinterpret_cast<uint4*>(&sAh[lrow][so]) = gAh[gi];
            *reinterpret_cast<uint4*>(&sAm[lrow][so]) = gAm[gi];
            *reinterpret_cast<uint4*>(&sWh[lrow][so]) = gWh[gi];
            *reinterpret_cast<uint4*>(&sWm[lrow][so]) = gWm[gi];
        }
        __syncthreads();

        #pragma unroll
        for (int kg = 0; kg < 2; kg++) {
            unsigned ah[2][4], am[2][4], bh[4][4], bm[4][4];
            // pass 1: Ah * Wh
            #pragma unroll
            for (int mt = 0; mt < 2; mt++) {
                uint32_t a = (uint32_t)__cvta_generic_to_shared(
                    &sAh[warpM * 32 + mt * 16 + rA][kg * 16 + cA]);
                LDMX4(ah[mt][0], ah[mt][1], ah[mt][2], ah[mt][3], a);
            }
            #pragma unroll
            for (int ng = 0; ng < 4; ng++) {
                uint32_t a = (uint32_t)__cvta_generic_to_shared(
                    &sWh[warpN * 64 + ng * 16 + rB][kg * 16 + cB]);
                LDMX4(bh[ng][0], bh[ng][1], bh[ng][2], bh[ng][3], a);
            }
            #pragma unroll
            for (int mt = 0; mt < 2; mt++)
                #pragma unroll
                for (int ng = 0; ng < 4; ng++) {
                    MMA16816(d[mt][2 * ng],     ah[mt], bh[ng][0], bh[ng][1]);
                    MMA16816(d[mt][2 * ng + 1], ah[mt], bh[ng][2], bh[ng][3]);
                }
            // pass 2: Ah * Wm
            #pragma unroll
            for (int ng = 0; ng < 4; ng++) {
                uint32_t a = (uint32_t)__cvta_generic_to_shared(
                    &sWm[warpN * 64 + ng * 16 + rB][kg * 16 + cB]);
                LDMX4(bm[ng][0], bm[ng][1], bm[ng][2], bm[ng][3], a);
            }
            #pragma unroll
            for (int mt = 0; mt < 2; mt++)
                #pragma unroll
                for (int ng = 0; ng < 4; ng++) {
                    MMA16816(d[mt][2 * ng],     ah[mt], bm[ng][0], bm[ng][1]);
                    MMA16816(d[mt][2 * ng + 1], ah[mt], bm[ng][2], bm[ng][3]);
                }
            // pass 3: Am * Wh
            #pragma unroll
            for (int mt = 0; mt < 2; mt++) {
                uint32_t a = (uint32_t)__cvta_generic_to_shared(
                    &sAm[warpM * 32 + mt * 16 + rA][kg * 16 + cA]);
                LDMX4(am[mt][0], am[mt][1], am[mt][2], am[mt][3], a);
            }
            #pragma unroll
            for (int mt = 0; mt < 2; mt++)
                #pragma unroll
                for (int ng = 0; ng < 4; ng++) {
                    MMA16816(d[mt][2 * ng],     am[mt], bh[ng][0], bh[ng][1]);
                    MMA16816(d[mt][2 * ng + 1], am[mt], bh[ng][2], bh[ng][3]);
                }
        }
        __syncthreads();
    }

    // epilogue
    const int l4 = lane >> 2;
    const int l2 = (lane & 3) * 2;
    #pragma unroll
    for (int mt = 0; mt < 2; mt++) {
        int m0 = mBase + warpM * 32 + mt * 16 + l4;
        int m1 = m0 + 8;
        bool v0 = (m0 < Nn), v1 = (m1 < Nn);
        float he0 = (v0 && g_counts[m0] > 0) ? 1.f : 0.f;
        float he1 = (v1 && g_counts[m1] > 0) ? 1.f : 0.f;
        #pragma unroll
        for (int nt = 0; nt < 8; nt++) {
            int col = warpN * 64 + nt * 8 + l2;
            float2 b2 = *reinterpret_cast<const float2*>(bn + col);
            float2 e2 = *reinterpret_cast<const float2*>(be + col);
            if (v0) {
                float2 o0 = make_float2(d[mt][nt][0] + b2.x + he0 * e2.x,
                                        d[mt][nt][1] + b2.y + he0 * e2.y);
                *reinterpret_cast<float2*>(out + (size_t)m0 * D + col) = o0;
            }
            if (v1) {
                float2 o1 = make_float2(d[mt][nt][2] + b2.x + he1 * e2.x,
                                        d[mt][nt][3] + b2.y + he1 * e2.y);
                *reinterpret_cast<float2*>(out + (size_t)m1 * D + col) = o1;
            }
        }
    }
}

// ---------------------------------------------------------------------------
extern "C" void kernel_launch(void* const* d_in, const int* in_sizes, int n_in,
                              void* d_out, int out_size)
{
    const float* nfeat = (const float*)d_in[0];
    const float* efeat = (const float*)d_in[1];
    const float* ew    = (const float*)d_in[2];
    const float* Wn    = (const float*)d_in[3];
    const float* bn    = (const float*)d_in[4];
    const float* We    = (const float*)d_in[5];
    const float* be    = (const float*)d_in[6];
    const int*   src   = (const int*)d_in[7];
    const int*   dst   = (const int*)d_in[8];
    float* out = (float*)d_out;

    int Nn = in_sizes[0] / D;     // 100000
    int E  = in_sizes[2];         // 1600000
    int nScanBlocks = (Nn + SCAN_B - 1) / SCAN_B;

    zero_counts<<<(Nn + 255) / 256, 256>>>(Nn);
    hist_kernel<<<(E + 255) / 256, 256>>>(dst, E);
    scan1<<<nScanBlocks, SCAN_B>>>(Nn);
    scan2<<<1, 128>>>(nScanBlocks);
    scan3<<<nScanBlocks, SCAN_B>>>(Nn);
    scatter_ids<<<(E + 255) / 256, 256>>>(dst, src, ew, E);
    wprep<<<128, 256>>>(Wn, We);
    aggregate_kernel<<<(Nn + 7) / 8, 256>>>(nfeat, efeat, Nn);
    gemm_mma<<<(Nn + 127) / 128, 256>>>(bn, be, out, Nn);
}

// round 9
// speedup vs baseline: 2.0401x; 1.1562x over previous
#include <cuda_runtime.h>
#include <cuda_bf16.h>
#include <cstddef>
#include <cstdint>

#define D 128
#define NODES_CAP 100000
#define EDGES_CAP 1600000
#define SCAN_B 1024

// ---------------- scratch (__device__ globals; no allocation) ---------------
__device__ int   g_counts[NODES_CAP];
__device__ int   g_offs  [NODES_CAP];
__device__ int   g_bsum  [128];
__device__ int4  g_swe   [EDGES_CAP];              // (src, ew bits, edge id, 0) sorted by dst
__device__ __nv_bfloat16 g_xh[(size_t)NODES_CAP * 256];  // X hi plane
__device__ __nv_bfloat16 g_xm[(size_t)NODES_CAP * 256];  // X mid plane
__device__ __nv_bfloat16 g_wh[128 * 256];                // Wcat hi   [o][k]
__device__ __nv_bfloat16 g_wm[128 * 256];                // Wcat mid  [o][k]

// ---------------------------------------------------------------------------
// prep: zero counts + weight split in one launch
// ---------------------------------------------------------------------------
__global__ __launch_bounds__(256) void prep_kernel(
    const float* __restrict__ Wn, const float* __restrict__ We,
    int n_nodes, int zblocks)
{
    if ((int)blockIdx.x < zblocks) {
        int i = blockIdx.x * 256 + threadIdx.x;
        if (i < n_nodes) g_counts[i] = 0;
    } else {
        int i = (blockIdx.x - zblocks) * 256 + threadIdx.x;
        if (i < 128 * 256) {
            int o = i >> 8, k = i & 255;
            float w = (k < 128) ? Wn[o * 128 + k] : We[o * 128 + (k - 128)];
            __nv_bfloat16 h = __float2bfloat16(w);
            g_wh[i] = h;
            g_wm[i] = __float2bfloat16(w - __bfloat162float(h));
        }
    }
}

__global__ __launch_bounds__(256) void hist_kernel(const int* __restrict__ dst, int E)
{
    int e = blockIdx.x * 256 + threadIdx.x;
    if (e < E) atomicAdd(&g_counts[dst[e]], 1);
}

// per-1024-block exclusive scan; g_bsum[b] = block total
__global__ __launch_bounds__(SCAN_B) void scan1(int n)
{
    __shared__ int wsum[32];
    int i = blockIdx.x * SCAN_B + threadIdx.x;
    int v = (i < n) ? g_counts[i] : 0;
    int x = v;
    #pragma unroll
    for (int d = 1; d < 32; d <<= 1) {
        int y = __shfl_up_sync(0xffffffffu, x, d);
        if ((threadIdx.x & 31) >= d) x += y;
    }
    if ((threadIdx.x & 31) == 31) wsum[threadIdx.x >> 5] = x;
    __syncthreads();
    if (threadIdx.x < 32) {
        int y = wsum[threadIdx.x];
        #pragma unroll
        for (int d = 1; d < 32; d <<= 1) {
            int z = __shfl_up_sync(0xffffffffu, y, d);
            if (threadIdx.x >= d) y += z;
        }
        wsum[threadIdx.x] = y;
    }
    __syncthreads();
    int base = (threadIdx.x >= 32) ? wsum[(threadIdx.x >> 5) - 1] : 0;
    int incl = base + x;
    if (i < n) g_offs[i] = incl - v;
    if (threadIdx.x == SCAN_B - 1) g_bsum[blockIdx.x] = incl;
}

// apply cross-block base: each block sums g_bsum[0..bid) itself (<=98 ints)
__global__ __launch_bounds__(SCAN_B) void scan_apply(int n)
{
    __shared__ int sbase;
    if (threadIdx.x < 32) {
        int acc = 0;
        for (int j = threadIdx.x; j < (int)blockIdx.x; j += 32) acc += g_bsum[j];
        #pragma unroll
        for (int d = 16; d > 0; d >>= 1) acc += __shfl_down_sync(0xffffffffu, acc, d);
        if (threadIdx.x == 0) sbase = acc;
    }
    __syncthreads();
    int i = blockIdx.x * SCAN_B + threadIdx.x;
    if (i < n) g_offs[i] += sbase;
}

__global__ __launch_bounds__(256) void scatter_ids(
    const int* __restrict__ dst, const int* __restrict__ src,
    const float* __restrict__ ew, int E)
{
    int e = blockIdx.x * 256 + threadIdx.x;
    if (e < E) {
        int p = atomicAdd(&g_offs[dst[e]], 1);
        g_swe[p] = make_int4(src[e], __float_as_int(ew[e]), e, 0);
    }
}

// ---------------------------------------------------------------------------
// Warp-per-node aggregation -> normalized X, written as bf16 hi/mid planes.
// Unroll 4 for MLP; __ldcs on streamed data to keep nfeat L2-resident.
// ---------------------------------------------------------------------------
__device__ __forceinline__ uint2 pack4_hi(float4 v, float4* resid)
{
    __nv_bfloat162 p0 = __floats2bfloat162_rn(v.x, v.y);
    __nv_bfloat162 p1 = __floats2bfloat162_rn(v.z, v.w);
    resid->x = v.x - __bfloat162float(__low2bfloat16(p0));
    resid->y = v.y - __bfloat162float(__high2bfloat16(p0));
    resid->z = v.z - __bfloat162float(__low2bfloat16(p1));
    resid->w = v.w - __bfloat162float(__high2bfloat16(p1));
    uint2 r;
    r.x = *reinterpret_cast<unsigned*>(&p0);
    r.y = *reinterpret_cast<unsigned*>(&p1);
    return r;
}
__device__ __forceinline__ uint2 pack4(float4 v)
{
    __nv_bfloat162 p0 = __floats2bfloat162_rn(v.x, v.y);
    __nv_bfloat162 p1 = __floats2bfloat162_rn(v.z, v.w);
    uint2 r;
    r.x = *reinterpret_cast<unsigned*>(&p0);
    r.y = *reinterpret_cast<unsigned*>(&p1);
    return r;
}

__global__ __launch_bounds__(256) void aggregate_kernel(
    const float* __restrict__ nfeat, const float* __restrict__ efeat, int Nn)
{
    int n = blockIdx.x * 8 + (threadIdx.x >> 5);
    if (n >= Nn) return;
    int lane = threadIdx.x & 31;

    int end = g_offs[n];
    int cnt = g_counts[n];
    int beg = end - cnt;

    const float4* nf4 = reinterpret_cast<const float4*>(nfeat);
    const float4* ef4 = reinterpret_cast<const float4*>(efeat);

    float4 aN = make_float4(0.f, 0.f, 0.f, 0.f);
    float4 aE = make_float4(0.f, 0.f, 0.f, 0.f);

    int i = beg;
    for (; i + 4 <= end; i += 4) {
        int4 q0 = __ldcs(g_swe + i);
        int4 q1 = __ldcs(g_swe + i + 1);
        int4 q2 = __ldcs(g_swe + i + 2);
        int4 q3 = __ldcs(g_swe + i + 3);
        float4 a0 = __ldg(nf4 + (size_t)q0.x * 32 + lane);
        float4 a1 = __ldg(nf4 + (size_t)q1.x * 32 + lane);
        float4 a2 = __ldg(nf4 + (size_t)q2.x * 32 + lane);
        float4 a3 = __ldg(nf4 + (size_t)q3.x * 32 + lane);
        float4 v0 = __ldcs(ef4 + (size_t)q0.z * 32 + lane);
        float4 v1 = __ldcs(ef4 + (size_t)q1.z * 32 + lane);
        float4 v2 = __ldcs(ef4 + (size_t)q2.z * 32 + lane);
        float4 v3 = __ldcs(ef4 + (size_t)q3.z * 32 + lane);
        float w0 = __int_as_float(q0.y), w1 = __int_as_float(q1.y);
        float w2 = __int_as_float(q2.y), w3 = __int_as_float(q3.y);
        aN.x += a0.x * w0 + a1.x * w1 + a2.x * w2 + a3.x * w3;
        aN.y += a0.y * w0 + a1.y * w1 + a2.y * w2 + a3.y * w3;
        aN.z += a0.z * w0 + a1.z * w1 + a2.z * w2 + a3.z * w3;
        aN.w += a0.w * w0 + a1.w * w1 + a2.w * w2 + a3.w * w3;
        aE.x += (v0.x + v1.x) + (v2.x + v3.x);
        aE.y += (v0.y + v1.y) + (v2.y + v3.y);
        aE.z += (v0.z + v1.z) + (v2.z + v3.z);
        aE.w += (v0.w + v1.w) + (v2.w + v3.w);
    }
    for (; i < end; i++) {
        int4 q = __ldcs(g_swe + i);
        float w = __int_as_float(q.y);
        float4 a = __ldg(nf4 + (size_t)q.x * 32 + lane);
        float4 v = __ldcs(ef4 + (size_t)q.z * 32 + lane);
        aN.x += a.x * w;  aN.y += a.y * w;  aN.z += a.z * w;  aN.w += a.w * w;
        aE.x += v.x;  aE.y += v.y;  aE.z += v.z;  aE.w += v.w;
    }

    float invD = 1.f / ((float)cnt + 1.f);
    float invE = 1.f / (float)max(cnt, 1);
    float4 f = __ldg(nf4 + (size_t)n * 32 + lane);

    float4 xn = make_float4((aN.x + 2.f * f.x) * invD, (aN.y + 2.f * f.y) * invD,
                            (aN.z + 2.f * f.z) * invD, (aN.w + 2.f * f.w) * invD);
    float4 xe = make_float4(aE.x * invE, aE.y * invE, aE.z * invE, aE.w * invE);

    uint2* xh = reinterpret_cast<uint2*>(g_xh + (size_t)n * 256);
    uint2* xm = reinterpret_cast<uint2*>(g_xm + (size_t)n * 256);
    float4 r;
    xh[lane] = pack4_hi(xn, &r);       xm[lane] = pack4(r);
    xh[32 + lane] = pack4_hi(xe, &r);  xm[32 + lane] = pack4(r);
}

// ---------------------------------------------------------------------------
// HMMA GEMM, cp.async double-buffered.
// Block: 128(M) x 128(N), 8 warps (4Mx2N), warp tile 32x64, K in 8 chunks of 32.
// Smem pitch 40 bf16 -> conflict-free ldmatrix. 2-stage pipeline, 80KB dyn smem.
// ---------------------------------------------------------------------------
#define LDMX4(r0, r1, r2, r3, addr)                                                \
    asm volatile("ldmatrix.sync.aligned.m8n8.x4.shared.b16 {%0,%1,%2,%3}, [%4];"   \
                 : "=r"(r0), "=r"(r1), "=r"(r2), "=r"(r3) : "r"(addr))

#define MMA16816(d, a, b0, b1)                                                     \
    asm volatile("mma.sync.aligned.m16n8k16.row.col.f32.bf16.bf16.f32 "            \
                 "{%0,%1,%2,%3},{%4,%5,%6,%7},{%8,%9},{%0,%1,%2,%3};"              \
                 : "+f"((d)[0]), "+f"((d)[1]), "+f"((d)[2]), "+f"((d)[3])          \
                 : "r"((a)[0]), "r"((a)[1]), "r"((a)[2]), "r"((a)[3]),             \
                   "r"(b0), "r"(b1))

#define CP16(dst, src)                                                             \
    asm volatile("cp.async.cg.shared.global [%0], [%1], 16;" :: "r"(dst), "l"(src))
#define CP_COMMIT() asm volatile("cp.async.commit_group;" ::: "memory")
#define CP_WAIT1()  asm volatile("cp.async.wait_group 1;" ::: "memory")
#define CP_WAIT0()  asm volatile("cp.async.wait_group 0;" ::: "memory")

#define PITCH 40
#define PLANE_ELEMS (128 * PITCH)
#define PLANE_BYTES (PLANE_ELEMS * 2)
#define GSMEM_TOTAL (8 * PLANE_BYTES)     // 81920

__global__ __launch_bounds__(256) void gemm_mma(
    const float* __restrict__ bn, const float* __restrict__ be,
    float* __restrict__ out, int Nn)
{
    extern __shared__ __nv_bfloat16 smem[];
    const uint32_t smem_b = (uint32_t)__cvta_generic_to_shared(smem);

    const int tid  = threadIdx.x;
    const int wid  = tid >> 5;
    const int lane = tid & 31;
    const int warpM = wid & 3;
    const int warpN = wid >> 2;
    const int mBase = blockIdx.x * 128;

    float d[2][8][4];
    #pragma unroll
    for (int mt = 0; mt < 2; mt++)
        #pragma unroll
        for (int nt = 0; nt < 8; nt++)
            #pragma unroll
            for (int c = 0; c < 4; c++) d[mt][nt][c] = 0.f;

    // loaders: 2 threads per row, each 2 x 16B of the 64B k-chunk row
    const int lrow = tid >> 1;
    const int lt   = (tid & 1) * 2;
    int arow = mBase + lrow; if (arow >= Nn) arow = Nn - 1;
    const uint4* gAh = reinterpret_cast<const uint4*>(g_xh + (size_t)arow * 256);
    const uint4* gAm = reinterpret_cast<const uint4*>(g_xm + (size_t)arow * 256);
    const uint4* gWh = reinterpret_cast<const uint4*>(g_wh + (size_t)lrow * 256);
    const uint4* gWm = reinterpret_cast<const uint4*>(g_wm + (size_t)lrow * 256);

    // plane order per buffer: Ah, Am, Wh, Wm
    auto issue = [&](int kc, int b) {
        #pragma unroll
        for (int t = 0; t < 2; t++) {
            int gi = kc * 4 + lt + t;
            uint32_t so = (uint32_t)(lrow * PITCH + (lt + t) * 8) * 2;
            uint32_t base = smem_b + (uint32_t)(b * 4) * PLANE_BYTES + so;
            CP16(base,                   gAh + gi);
            CP16(base + PLANE_BYTES,     gAm + gi);
            CP16(base + 2 * PLANE_BYTES, gWh + gi);
            CP16(base + 3 * PLANE_BYTES, gWm + gi);
        }
    };

    const int rA = (lane & 7) + ((lane >> 3) & 1) * 8;
    const int cA = (lane >> 4) * 8;
    const int rB = (lane & 7) + ((lane >> 4) & 1) * 8;
    const int cB = ((lane >> 3) & 1) * 8;

    issue(0, 0);
    CP_COMMIT();

    for (int kc = 0; kc < 8; kc++) {
        int b = kc & 1;
        if (kc < 7) {
            issue(kc + 1, b ^ 1);
            CP_COMMIT();
            CP_WAIT1();
        } else {
            CP_WAIT0();
        }
        __syncthreads();

        uint32_t pAh = smem_b + (uint32_t)(b * 4) * PLANE_BYTES;
        uint32_t pAm = pAh + PLANE_BYTES;
        uint32_t pWh = pAh + 2 * PLANE_BYTES;
        uint32_t pWm = pAh + 3 * PLANE_BYTES;

        #pragma unroll
        for (int kg = 0; kg < 2; kg++) {
            unsigned ah[2][4], am[2][4], bh[4][4], bm[4][4];
            #pragma unroll
            for (int mt = 0; mt < 2; mt++) {
                uint32_t a = pAh + (uint32_t)((warpM * 32 + mt * 16 + rA) * PITCH
                                              + kg * 16 + cA) * 2;
                LDMX4(ah[mt][0], ah[mt][1], ah[mt][2], ah[mt][3], a);
            }
            #pragma unroll
            for (int ng = 0; ng < 4; ng++) {
                uint32_t a = pWh + (uint32_t)((warpN * 64 + ng * 16 + rB) * PITCH
                                              + kg * 16 + cB) * 2;
                LDMX4(bh[ng][0], bh[ng][1], bh[ng][2], bh[ng][3], a);
            }
            #pragma unroll
            for (int mt = 0; mt < 2; mt++)
                #pragma unroll
                for (int ng = 0; ng < 4; ng++) {
                    MMA16816(d[mt][2 * ng],     ah[mt], bh[ng][0], bh[ng][1]);
                    MMA16816(d[mt][2 * ng + 1], ah[mt], bh[ng][2], bh[ng][3]);
                }
            #pragma unroll
            for (int ng = 0; ng < 4; ng++) {
                uint32_t a = pWm + (uint32_t)((warpN * 64 + ng * 16 + rB) * PITCH
                                              + kg * 16 + cB) * 2;
                LDMX4(bm[ng][0], bm[ng][1], bm[ng][2], bm[ng][3], a);
            }
            #pragma unroll
            for (int mt = 0; mt < 2; mt++)
                #pragma unroll
                for (int ng = 0; ng < 4; ng++) {
                    MMA16816(d[mt][2 * ng],     ah[mt], bm[ng][0], bm[ng][1]);
                    MMA16816(d[mt][2 * ng + 1], ah[mt], bm[ng][2], bm[ng][3]);
                }
            #pragma unroll
            for (int mt = 0; mt < 2; mt++) {
                uint32_t a = pAm + (uint32_t)((warpM * 32 + mt * 16 + rA) * PITCH
                                              + kg * 16 + cA) * 2;
                LDMX4(am[mt][0], am[mt][1], am[mt][2], am[mt][3], a);
            }
            #pragma unroll
            for (int mt = 0; mt < 2; mt++)
                #pragma unroll
                for (int ng = 0; ng < 4; ng++) {
                    MMA16816(d[mt][2 * ng],     am[mt], bh[ng][0], bh[ng][1]);
                    MMA16816(d[mt][2 * ng + 1], am[mt], bh[ng][2], bh[ng][3]);
                }
        }
        __syncthreads();
    }

    // epilogue
    const int l4 = lane >> 2;
    const int l2 = (lane & 3) * 2;
    #pragma unroll
    for (int mt = 0; mt < 2; mt++) {
        int m0 = mBase + warpM * 32 + mt * 16 + l4;
        int m1 = m0 + 8;
        bool v0 = (m0 < Nn), v1 = (m1 < Nn);
        float he0 = (v0 && g_counts[m0] > 0) ? 1.f : 0.f;
        float he1 = (v1 && g_counts[m1] > 0) ? 1.f : 0.f;
        #pragma unroll
        for (int nt = 0; nt < 8; nt++) {
            int col = warpN * 64 + nt * 8 + l2;
            float2 b2 = *reinterpret_cast<const float2*>(bn + col);
            float2 e2 = *reinterpret_cast<const float2*>(be + col);
            if (v0) {
                float2 o0 = make_float2(d[mt][nt][0] + b2.x + he0 * e2.x,
                                        d[mt][nt][1] + b2.y + he0 * e2.y);
                *reinterpret_cast<float2*>(out + (size_t)m0 * D + col) = o0;
            }
            if (v1) {
                float2 o1 = make_float2(d[mt][nt][2] + b2.x + he1 * e2.x,
                                        d[mt][nt][3] + b2.y + he1 * e2.y);
                *reinterpret_cast<float2*>(out + (size_t)m1 * D + col) = o1;
            }
        }
    }
}

// ---------------------------------------------------------------------------
extern "C" void kernel_launch(void* const* d_in, const int* in_sizes, int n_in,
                              void* d_out, int out_size)
{
    const float* nfeat = (const float*)d_in[0];
    const float* efeat = (const float*)d_in[1];
    const float* ew    = (const float*)d_in[2];
    const float* Wn    = (const float*)d_in[3];
    const float* bn    = (const float*)d_in[4];
    const float* We    = (const float*)d_in[5];
    const float* be    = (const float*)d_in[6];
    const int*   src   = (const int*)d_in[7];
    const int*   dst   = (const int*)d_in[8];
    float* out = (float*)d_out;

    int Nn = in_sizes[0] / D;     // 100000
    int E  = in_sizes[2];         // 1600000
    int nScanBlocks = (Nn + SCAN_B - 1) / SCAN_B;
    int zblocks = (Nn + 255) / 256;

    cudaFuncSetAttribute(gemm_mma, cudaFuncAttributeMaxDynamicSharedMemorySize,
                         GSMEM_TOTAL);

    prep_kernel<<<zblocks + 128, 256>>>(Wn, We, Nn, zblocks);
    hist_kernel<<<(E + 255) / 256, 256>>>(dst, E);
    scan1<<<nScanBlocks, SCAN_B>>>(Nn);
    scan_apply<<<nScanBlocks, SCAN_B>>>(Nn);
    scatter_ids<<<(E + 255) / 256, 256>>>(dst, src, ew, E);
    aggregate_kernel<<<(Nn + 7) / 8, 256>>>(nfeat, efeat, Nn);
    gemm_mma<<<(Nn + 127) / 128, 256, GSMEM_TOTAL>>>(bn, be, out, Nn);
}